// round 8
// baseline (speedup 1.0000x reference)
#include <cuda_runtime.h>
#include <cuda_bf16.h>
#include <stdint.h>

#define NN 100000
#define EE 800000
#define HD 128
#define PITCH 136   // padded smem row (bf16 elems) -> conflict-free LDSM

// ---------------- scratch (static device memory; no allocs) ----------------
__device__ float g_featsrc[NN * HD];
__device__ float g_skip[NN * HD];
__device__ float g_el[NN * 4];
__device__ float g_er[NN * 4];
__device__ int   g_deg[NN];          // zero-init; k_scan1 re-zeroes after read
__device__ int   g_rowptr[NN + 1];
__device__ int   g_cursor[NN];       // set to rowptr by k_scan3
__device__ int   g_csrc[EE];
__device__ __nv_bfloat16 g_Wbh[256 * 128];  // [W_src; W_skip] hi
__device__ __nv_bfloat16 g_Wbl[256 * 128];  // lo residual
__device__ float g_bcat[256];
__device__ int   g_bsum[128];
__device__ int   g_boff[128];

// ---------------- mma helpers -----------------------------------------------
__device__ __forceinline__ void ldsm4(uint32_t* d, const void* p) {
    uint32_t a = (uint32_t)__cvta_generic_to_shared(p);
    asm volatile("ldmatrix.sync.aligned.m8n8.x4.shared.b16 {%0,%1,%2,%3}, [%4];"
                 : "=r"(d[0]), "=r"(d[1]), "=r"(d[2]), "=r"(d[3]) : "r"(a));
}

__device__ __forceinline__ void mma_bf16(float* c, const uint32_t* a,
                                         uint32_t b0, uint32_t b1) {
    asm volatile(
        "mma.sync.aligned.m16n8k16.row.col.f32.bf16.bf16.f32 "
        "{%0,%1,%2,%3}, {%4,%5,%6,%7}, {%8,%9}, {%0,%1,%2,%3};"
        : "+f"(c[0]), "+f"(c[1]), "+f"(c[2]), "+f"(c[3])
        : "r"(a[0]), "r"(a[1]), "r"(a[2]), "r"(a[3]), "r"(b0), "r"(b1));
}

// ---------------- K0: prep (weights split) + degree count, fused ------------
__global__ void k_prepdeg(const float* __restrict__ W_src, const float* __restrict__ b_src,
                          const float* __restrict__ W_skip, const float* __restrict__ b_skip,
                          const int* __restrict__ dst) {
    int i = blockIdx.x * blockDim.x + threadIdx.x;
    if (i < 128 * 128) {
        float ws = W_src[i];
        __nv_bfloat16 h = __float2bfloat16(ws);
        g_Wbh[i] = h;
        g_Wbl[i] = __float2bfloat16(ws - __bfloat162float(h));
        float wk = W_skip[i];
        __nv_bfloat16 h2 = __float2bfloat16(wk);
        g_Wbh[16384 + i] = h2;
        g_Wbl[16384 + i] = __float2bfloat16(wk - __bfloat162float(h2));
    }
    if (i < 128) {
        g_bcat[i] = b_src[i];
        g_bcat[128 + i] = b_skip[i];
    }
    if (i < EE) atomicAdd(&g_deg[dst[i]], 1);
}

// ---------------- K4a: per-block scan; zeroes g_deg --------------------------
__global__ void k_scan1() {
    __shared__ int wsum[32];
    const int t = threadIdx.x;
    const int b = blockIdx.x;
    const int lane = t & 31, w = t >> 5;
    const int i = b * 1024 + t;
    int v = (i < NN) ? g_deg[i] : 0;
    if (i < NN) g_deg[i] = 0;
    int x = v;
#pragma unroll
    for (int off = 1; off < 32; off <<= 1) {
        int y = __shfl_up_sync(0xffffffffu, x, off);
        if (lane >= off) x += y;
    }
    if (lane == 31) wsum[w] = x;
    __syncthreads();
    if (w == 0) {
        int y = wsum[lane];
#pragma unroll
        for (int off = 1; off < 32; off <<= 1) {
            int z = __shfl_up_sync(0xffffffffu, y, off);
            if (lane >= off) y += z;
        }
        wsum[lane] = y;
    }
    __syncthreads();
    int incl = x + (w > 0 ? wsum[w - 1] : 0);
    if (i < NN) g_rowptr[i] = incl - v;
    if (t == 1023) g_bsum[b] = incl;
}

// ---------------- K4b: scan of 98 block sums ---------------------------------
__global__ void k_scan2() {
    __shared__ int wsum[4];
    const int t = threadIdx.x;  // 128
    const int lane = t & 31, w = t >> 5;
    const int NB = 98;
    int v = (t < NB) ? g_bsum[t] : 0;
    int x = v;
#pragma unroll
    for (int off = 1; off < 32; off <<= 1) {
        int y = __shfl_up_sync(0xffffffffu, x, off);
        if (lane >= off) x += y;
    }
    if (lane == 31) wsum[w] = x;
    __syncthreads();
    int carry = 0;
#pragma unroll
    for (int k = 0; k < 4; k++) if (k < w) carry += wsum[k];
    int incl = x + carry;
    if (t < NB) g_boff[t] = incl - v;
    if (t == NB - 1) g_rowptr[NN] = incl;
}

// ---------------- K1: mma.sync GEMM, M=64 x N=128 per CTA, 2 CTAs/SM --------
// grid (1563, 2): y=0 -> featsrc (W_src) + fused el/er, y=1 -> skip (W_skip).
// bf16 3-term split: C = Ah*Bh + Ah*Bl + Al*Bh, fp32 accumulate.
__global__ void __launch_bounds__(256, 2) k_gemm(const float* __restrict__ feat,
                                                 const float* __restrict__ attn_l,
                                                 const float* __restrict__ attn_r) {
    extern __shared__ __nv_bfloat16 smem[];
    __nv_bfloat16* sAh = smem;                       // 64 x PITCH
    __nv_bfloat16* sAl = sAh + 64 * PITCH;
    __nv_bfloat16* sBh = sAl + 64 * PITCH;           // 128 x PITCH
    __nv_bfloat16* sBl = sBh + 128 * PITCH;
    __shared__ float sEl[4][64];
    __shared__ float sEr[4][64];

    const int t = threadIdx.x;
    const int row0 = blockIdx.x * 64;
    const int nblk = blockIdx.y;

    // ---- A tile (fp32 -> bf16 hi/lo): 64x128 = 2048 float4, 256 thr x 8 ----
#pragma unroll
    for (int i = 0; i < 8; i++) {
        int id = t + i * 256;             // 0..2047
        int r = id >> 5;                  // 0..63
        int q = (id & 31) << 2;           // 0..124
        float4 v = make_float4(0.f, 0.f, 0.f, 0.f);
        if (row0 + r < NN)
            v = *(const float4*)&feat[(size_t)(row0 + r) * 128 + q];
        __nv_bfloat16 h0 = __float2bfloat16(v.x);
        __nv_bfloat16 h1 = __float2bfloat16(v.y);
        __nv_bfloat16 h2 = __float2bfloat16(v.z);
        __nv_bfloat16 h3 = __float2bfloat16(v.w);
        __nv_bfloat16 l0 = __float2bfloat16(v.x - __bfloat162float(h0));
        __nv_bfloat16 l1 = __float2bfloat16(v.y - __bfloat162float(h1));
        __nv_bfloat16 l2 = __float2bfloat16(v.z - __bfloat162float(h2));
        __nv_bfloat16 l3 = __float2bfloat16(v.w - __bfloat162float(h3));
        __nv_bfloat162* ph = (__nv_bfloat162*)&sAh[r * PITCH + q];
        ph[0] = __nv_bfloat162(h0, h1); ph[1] = __nv_bfloat162(h2, h3);
        __nv_bfloat162* pl = (__nv_bfloat162*)&sAl[r * PITCH + q];
        pl[0] = __nv_bfloat162(l0, l1); pl[1] = __nv_bfloat162(l2, l3);
    }
    // ---- B tile (pre-split bf16): 128 rows of this W block -----------------
#pragma unroll
    for (int i = 0; i < 16; i++) {
        int id = t + i * 256;             // 0..4095
        int r = id >> 5;                  // 0..127
        int q = (id & 31) << 2;
        *(uint2*)&sBh[r * PITCH + q] = *(const uint2*)&g_Wbh[(nblk * 128 + r) * 128 + q];
        *(uint2*)&sBl[r * PITCH + q] = *(const uint2*)&g_Wbl[(nblk * 128 + r) * 128 + q];
    }
    __syncthreads();

    // ---- warp tiling: 8 warps in 2(M) x 4(N); each 32(M) x 32(N) ----
    const int wid = t >> 5, lane = t & 31;
    const int m0w = (wid >> 2) * 32;
    const int n0w = (wid & 3) * 32;

    float acc[2][4][4];
#pragma unroll
    for (int mt = 0; mt < 2; mt++)
#pragma unroll
        for (int nt = 0; nt < 4; nt++)
#pragma unroll
            for (int f = 0; f < 4; f++) acc[mt][nt][f] = 0.f;

#pragma unroll
    for (int kc = 0; kc < 8; kc++) {
        const int k0 = kc * 16;
        uint32_t a_h[2][4], a_l[2][4];
#pragma unroll
        for (int mt = 0; mt < 2; mt++) {
            int r = m0w + mt * 16 + (lane & 7) + ((lane >> 3) & 1) * 8;
            int c = k0 + (lane >> 4) * 8;
            ldsm4(a_h[mt], &sAh[r * PITCH + c]);
            ldsm4(a_l[mt], &sAl[r * PITCH + c]);
        }
        uint32_t b_h[2][4], b_l[2][4];
#pragma unroll
        for (int np = 0; np < 2; np++) {
            int r = n0w + np * 16 + (lane & 7) + (lane >> 4) * 8;
            int c = k0 + ((lane >> 3) & 1) * 8;
            ldsm4(b_h[np], &sBh[r * PITCH + c]);
            ldsm4(b_l[np], &sBl[r * PITCH + c]);
        }
#pragma unroll
        for (int mt = 0; mt < 2; mt++)
#pragma unroll
            for (int nt = 0; nt < 4; nt++) {
                uint32_t bh0 = b_h[nt >> 1][(nt & 1) * 2];
                uint32_t bh1 = b_h[nt >> 1][(nt & 1) * 2 + 1];
                uint32_t bl0 = b_l[nt >> 1][(nt & 1) * 2];
                uint32_t bl1 = b_l[nt >> 1][(nt & 1) * 2 + 1];
                mma_bf16(acc[mt][nt], a_h[mt], bh0, bh1);
                mma_bf16(acc[mt][nt], a_h[mt], bl0, bl1);
                mma_bf16(acc[mt][nt], a_l[mt], bh0, bh1);
            }
    }

    // ---- epilogue: bias + store; fused el/er for nblk==0 --------------------
    float* outp = nblk ? g_skip : g_featsrc;
    const int g = lane >> 2, c2 = (lane & 3) * 2;
    const int head = wid & 3;      // this warp's 32 cols = one head
    float elp[2][2] = {{0.f, 0.f}, {0.f, 0.f}};
    float erp[2][2] = {{0.f, 0.f}, {0.f, 0.f}};
#pragma unroll
    for (int mt = 0; mt < 2; mt++) {
        int rbase = row0 + m0w + mt * 16 + g;
#pragma unroll
        for (int nt = 0; nt < 4; nt++) {
            int col = n0w + nt * 8 + c2;
            float b0 = g_bcat[nblk * 128 + col];
            float b1 = g_bcat[nblk * 128 + col + 1];
            float f0 = acc[mt][nt][0] + b0, f1 = acc[mt][nt][1] + b1;
            float f2 = acc[mt][nt][2] + b0, f3 = acc[mt][nt][3] + b1;
            if (rbase < NN)
                *(float2*)&outp[(size_t)rbase * 128 + col] = make_float2(f0, f1);
            if (rbase + 8 < NN)
                *(float2*)&outp[(size_t)(rbase + 8) * 128 + col] = make_float2(f2, f3);
            if (nblk == 0) {
                float al0 = attn_l[col], al1 = attn_l[col + 1];
                float ar0 = attn_r[col], ar1 = attn_r[col + 1];
                elp[mt][0] += f0 * al0 + f1 * al1;
                elp[mt][1] += f2 * al0 + f3 * al1;
                erp[mt][0] += f0 * ar0 + f1 * ar1;
                erp[mt][1] += f2 * ar0 + f3 * ar1;
            }
        }
    }
    if (nblk == 0) {
        // reduce across the lane quad (lanes sharing g)
#pragma unroll
        for (int mt = 0; mt < 2; mt++)
#pragma unroll
            for (int hf = 0; hf < 2; hf++) {
                elp[mt][hf] += __shfl_xor_sync(0xffffffffu, elp[mt][hf], 1);
                elp[mt][hf] += __shfl_xor_sync(0xffffffffu, elp[mt][hf], 2);
                erp[mt][hf] += __shfl_xor_sync(0xffffffffu, erp[mt][hf], 1);
                erp[mt][hf] += __shfl_xor_sync(0xffffffffu, erp[mt][hf], 2);
            }
        if ((lane & 3) == 0) {
#pragma unroll
            for (int mt = 0; mt < 2; mt++)
#pragma unroll
                for (int hf = 0; hf < 2; hf++) {
                    int lr = m0w + mt * 16 + g + hf * 8;   // 0..63
                    sEl[head][lr] = elp[mt][hf];
                    sEr[head][lr] = erp[mt][hf];
                }
        }
        __syncthreads();
        // 256 threads: 64 rows x 4 heads
        int lr = t >> 2, h = t & 3;
        if (row0 + lr < NN) {
            g_el[(row0 + lr) * 4 + h] = sEl[h][lr];
            g_er[(row0 + lr) * 4 + h] = sEr[h][lr];
        }
    }
}

// ---------------- K4c: add block offsets, init cursor ------------------------
__global__ void k_scan3() {
    int i = blockIdx.x * 1024 + threadIdx.x;
    if (i < NN) {
        int v = g_rowptr[i] + g_boff[blockIdx.x];
        g_rowptr[i] = v;
        g_cursor[i] = v;
    }
}

// ---------------- K5: fill CSR (cursor holds absolute slot) -----------------
__global__ void k_fill(const int* __restrict__ src, const int* __restrict__ dst) {
    int i = blockIdx.x * blockDim.x + threadIdx.x;
    if (i < EE) {
        int slot = atomicAdd(&g_cursor[dst[i]], 1);
        g_csrc[slot] = src[i];
    }
}

// ---------------- K6: per-node softmax + aggregate + gate + LN + PReLU ------
// exp() without max-subtraction (logits O(5), no overflow; shift-invariant).
// 4-way unrolled gather for MLP on the latency chain.
__global__ void k_node(const float* __restrict__ W_gate, const float* __restrict__ b_gate,
                       const float* __restrict__ ln_g, const float* __restrict__ ln_b,
                       const float* __restrict__ prelu_a, float* __restrict__ out) {
    int gid = blockIdx.x * blockDim.x + threadIdx.x;
    int n = gid >> 5;
    int lane = threadIdx.x & 31;
    if (n >= NN) return;
    const int h = lane >> 3;

    int start = g_rowptr[n];
    int end = g_rowptr[n + 1];
    int deg = end - start;
    float erh = g_er[n * 4 + h];

    float4 acc = make_float4(0.f, 0.f, 0.f, 0.f);
    float sumex = 0.f;
    int k = start;
    for (; k + 3 < end; k += 4) {
        int s0 = g_csrc[k], s1 = g_csrc[k + 1];
        int s2 = g_csrc[k + 2], s3 = g_csrc[k + 3];
        float e0 = g_el[s0 * 4 + h] + erh;
        float e1 = g_el[s1 * 4 + h] + erh;
        float e2 = g_el[s2 * 4 + h] + erh;
        float e3 = g_el[s3 * 4 + h] + erh;
        float4 f0 = *(const float4*)&g_featsrc[(size_t)s0 * 128 + 4 * lane];
        float4 f1 = *(const float4*)&g_featsrc[(size_t)s1 * 128 + 4 * lane];
        float4 f2 = *(const float4*)&g_featsrc[(size_t)s2 * 128 + 4 * lane];
        float4 f3 = *(const float4*)&g_featsrc[(size_t)s3 * 128 + 4 * lane];
        e0 = (e0 >= 0.f) ? e0 : 0.2f * e0;
        e1 = (e1 >= 0.f) ? e1 : 0.2f * e1;
        e2 = (e2 >= 0.f) ? e2 : 0.2f * e2;
        e3 = (e3 >= 0.f) ? e3 : 0.2f * e3;
        float x0 = __expf(e0), x1 = __expf(e1), x2 = __expf(e2), x3 = __expf(e3);
        sumex += x0 + x1 + x2 + x3;
        acc.x += x0 * f0.x + x1 * f1.x + x2 * f2.x + x3 * f3.x;
        acc.y += x0 * f0.y + x1 * f1.y + x2 * f2.y + x3 * f3.y;
        acc.z += x0 * f0.z + x1 * f1.z + x2 * f2.z + x3 * f3.z;
        acc.w += x0 * f0.w + x1 * f1.w + x2 * f2.w + x3 * f3.w;
    }
    for (; k < end; k++) {
        int s = g_csrc[k];
        float e = g_el[s * 4 + h] + erh;
        e = (e >= 0.f) ? e : 0.2f * e;
        float ex = __expf(e);
        sumex += ex;
        float4 f = *(const float4*)&g_featsrc[(size_t)s * 128 + 4 * lane];
        acc.x += ex * f.x; acc.y += ex * f.y;
        acc.z += ex * f.z; acc.w += ex * f.w;
    }
    float4 rst;
    if (deg > 0) {
        float inv = 1.0f / sumex;
        rst = make_float4(acc.x * inv, acc.y * inv, acc.z * inv, acc.w * inv);
    } else {
        rst = make_float4(0.f, 0.f, 0.f, 0.f);
    }

    float4 sk = *(const float4*)&g_skip[(size_t)n * 128 + 4 * lane];
    float4 w1 = *(const float4*)&W_gate[4 * lane];
    float4 w2 = *(const float4*)&W_gate[128 + 4 * lane];
    float4 w3 = *(const float4*)&W_gate[256 + 4 * lane];
    float gacc = rst.x * w1.x + rst.y * w1.y + rst.z * w1.z + rst.w * w1.w
               + sk.x * w2.x + sk.y * w2.y + sk.z * w2.z + sk.w * w2.w
               + (rst.x - sk.x) * w3.x + (rst.y - sk.y) * w3.y
               + (rst.z - sk.z) * w3.z + (rst.w - sk.w) * w3.w;
#pragma unroll
    for (int off = 16; off >= 1; off >>= 1)
        gacc += __shfl_xor_sync(0xffffffffu, gacc, off);
    float gate = 1.0f / (1.0f + __expf(-(gacc + b_gate[0])));
    float4 x = make_float4(gate * rst.x + (1.f - gate) * sk.x,
                           gate * rst.y + (1.f - gate) * sk.y,
                           gate * rst.z + (1.f - gate) * sk.z,
                           gate * rst.w + (1.f - gate) * sk.w);

    float s1 = x.x + x.y + x.z + x.w;
    float s2 = x.x * x.x + x.y * x.y + x.z * x.z + x.w * x.w;
#pragma unroll
    for (int off = 16; off >= 1; off >>= 1) {
        s1 += __shfl_xor_sync(0xffffffffu, s1, off);
        s2 += __shfl_xor_sync(0xffffffffu, s2, off);
    }
    float mean = s1 * (1.0f / 128.0f);
    float var = s2 * (1.0f / 128.0f) - mean * mean;
    float inv = rsqrtf(var + 1e-5f);
    float4 g4 = *(const float4*)&ln_g[4 * lane];
    float4 b4 = *(const float4*)&ln_b[4 * lane];
    float alpha = prelu_a[0];
    float y0 = (x.x - mean) * inv * g4.x + b4.x;
    float y1 = (x.y - mean) * inv * g4.y + b4.y;
    float y2 = (x.z - mean) * inv * g4.z + b4.z;
    float y3 = (x.w - mean) * inv * g4.w + b4.w;
    y0 = (y0 >= 0.f) ? y0 : alpha * y0;
    y1 = (y1 >= 0.f) ? y1 : alpha * y1;
    y2 = (y2 >= 0.f) ? y2 : alpha * y2;
    y3 = (y3 >= 0.f) ? y3 : alpha * y3;
    *(float4*)&out[(size_t)n * 128 + 4 * lane] = make_float4(y0, y1, y2, y3);
}

// ---------------- launcher ---------------------------------------------------
extern "C" void kernel_launch(void* const* d_in, const int* in_sizes, int n_in,
                              void* d_out, int out_size) {
    const float* feat    = (const float*)d_in[0];
    const int*   src     = (const int*)d_in[1];
    const int*   dst     = (const int*)d_in[2];
    const float* W_src   = (const float*)d_in[3];
    const float* b_src   = (const float*)d_in[4];
    const float* attn_l  = (const float*)d_in[5];
    const float* attn_r  = (const float*)d_in[6];
    const float* W_skip  = (const float*)d_in[7];
    const float* b_skip  = (const float*)d_in[8];
    const float* W_gate  = (const float*)d_in[9];
    const float* b_gate  = (const float*)d_in[10];
    const float* ln_g    = (const float*)d_in[11];
    const float* ln_b    = (const float*)d_in[12];
    const float* prelu_a = (const float*)d_in[13];
    float* out = (float*)d_out;

    // smem: (64 + 64 + 128 + 128) * PITCH * 2B = 104448
    const int GEMM_SMEM = (64 + 64 + 128 + 128) * PITCH * (int)sizeof(__nv_bfloat16);
    static int smem_set = 0;
    if (!smem_set) {
        cudaFuncSetAttribute(k_gemm, cudaFuncAttributeMaxDynamicSharedMemorySize, GEMM_SMEM);
        smem_set = 1;
    }

    // k_gemm kept as the 4th launch (the one ncu captures).
    k_prepdeg<<<(EE + 511) / 512, 512>>>(W_src, b_src, W_skip, b_skip, dst);
    k_scan1<<<98, 1024>>>();
    k_scan2<<<1, 128>>>();
    k_gemm<<<dim3((NN + 63) / 64, 2), 256, GEMM_SMEM>>>(feat, attn_l, attn_r);
    k_scan3<<<98, 1024>>>();
    k_fill<<<(EE + 255) / 256, 256>>>(src, dst);
    k_node<<<(NN * 32 + 255) / 256, 256>>>(W_gate, b_gate, ln_g, ln_b, prelu_a, out);
}

// round 10
// speedup vs baseline: 1.1261x; 1.1261x over previous
#include <cuda_runtime.h>
#include <cuda_bf16.h>
#include <cuda_fp16.h>
#include <stdint.h>

#define NN 100000
#define EE 800000
#define HD 128
#define PITCH 136   // padded smem row (bf16 elems) -> conflict-free LDSM

// ---------------- scratch (static device memory; no allocs) ----------------
__device__ __half g_fsh[NN * HD];    // featsrc in fp16 (gather payload)
__device__ float g_skip[NN * HD];
__device__ float g_el[NN * 4];
__device__ float g_er[NN * 4];
__device__ int   g_deg[NN];          // zero-init; k_scan1 re-zeroes after read
__device__ int   g_rowptr[NN];       // rebuilt every replay; consumed by fill
__device__ int   g_csrc[EE];
__device__ __nv_bfloat16 g_Wbh[256 * 128];  // [W_src; W_skip] hi
__device__ __nv_bfloat16 g_Wbl[256 * 128];  // lo residual
__device__ float g_bcat[256];
__device__ int   g_bsum[128];
__device__ int   g_boff[128];

// ---------------- mma helpers -----------------------------------------------
__device__ __forceinline__ void ldsm4(uint32_t* d, const void* p) {
    uint32_t a = (uint32_t)__cvta_generic_to_shared(p);
    asm volatile("ldmatrix.sync.aligned.m8n8.x4.shared.b16 {%0,%1,%2,%3}, [%4];"
                 : "=r"(d[0]), "=r"(d[1]), "=r"(d[2]), "=r"(d[3]) : "r"(a));
}

__device__ __forceinline__ void mma_bf16(float* c, const uint32_t* a,
                                         uint32_t b0, uint32_t b1) {
    asm volatile(
        "mma.sync.aligned.m16n8k16.row.col.f32.bf16.bf16.f32 "
        "{%0,%1,%2,%3}, {%4,%5,%6,%7}, {%8,%9}, {%0,%1,%2,%3};"
        : "+f"(c[0]), "+f"(c[1]), "+f"(c[2]), "+f"(c[3])
        : "r"(a[0]), "r"(a[1]), "r"(a[2]), "r"(a[3]), "r"(b0), "r"(b1));
}

// ---------------- K0: prep (weights split) + degree count, fused ------------
__global__ void k_prepdeg(const float* __restrict__ W_src, const float* __restrict__ b_src,
                          const float* __restrict__ W_skip, const float* __restrict__ b_skip,
                          const int* __restrict__ dst) {
    int i = blockIdx.x * blockDim.x + threadIdx.x;
    if (i < 128 * 128) {
        float ws = W_src[i];
        __nv_bfloat16 h = __float2bfloat16(ws);
        g_Wbh[i] = h;
        g_Wbl[i] = __float2bfloat16(ws - __bfloat162float(h));
        float wk = W_skip[i];
        __nv_bfloat16 h2 = __float2bfloat16(wk);
        g_Wbh[16384 + i] = h2;
        g_Wbl[16384 + i] = __float2bfloat16(wk - __bfloat162float(h2));
    }
    if (i < 128) {
        g_bcat[i] = b_src[i];
        g_bcat[128 + i] = b_skip[i];
    }
    if (i < EE) atomicAdd(&g_deg[dst[i]], 1);
}

// ---------------- K4a: per-block scan; zeroes g_deg --------------------------
__global__ void k_scan1() {
    __shared__ int wsum[32];
    const int t = threadIdx.x;
    const int b = blockIdx.x;
    const int lane = t & 31, w = t >> 5;
    const int i = b * 1024 + t;
    int v = (i < NN) ? g_deg[i] : 0;
    if (i < NN) g_deg[i] = 0;
    int x = v;
#pragma unroll
    for (int off = 1; off < 32; off <<= 1) {
        int y = __shfl_up_sync(0xffffffffu, x, off);
        if (lane >= off) x += y;
    }
    if (lane == 31) wsum[w] = x;
    __syncthreads();
    if (w == 0) {
        int y = wsum[lane];
#pragma unroll
        for (int off = 1; off < 32; off <<= 1) {
            int z = __shfl_up_sync(0xffffffffu, y, off);
            if (lane >= off) y += z;
        }
        wsum[lane] = y;
    }
    __syncthreads();
    int incl = x + (w > 0 ? wsum[w - 1] : 0);
    if (i < NN) g_rowptr[i] = incl - v;   // exclusive within block
    if (t == 1023) g_bsum[b] = incl;
}

// ---------------- K4b: scan of 98 block sums ---------------------------------
__global__ void k_scan2() {
    __shared__ int wsum[4];
    const int t = threadIdx.x;  // 128
    const int lane = t & 31, w = t >> 5;
    const int NB = 98;
    int v = (t < NB) ? g_bsum[t] : 0;
    int x = v;
#pragma unroll
    for (int off = 1; off < 32; off <<= 1) {
        int y = __shfl_up_sync(0xffffffffu, x, off);
        if (lane >= off) x += y;
    }
    if (lane == 31) wsum[w] = x;
    __syncthreads();
    int carry = 0;
#pragma unroll
    for (int k = 0; k < 4; k++) if (k < w) carry += wsum[k];
    int incl = x + carry;
    if (t < NB) g_boff[t] = incl - v;
}

// ---------------- K1: mma.sync GEMM, M=64 x N=128 per CTA -------------------
// grid (2, 1563): x=0 -> featsrc(fp16) + fused el/er, x=1 -> skip (fp32).
// Adjacent blockIdx.x pair shares the A tile -> 2nd read hits L2.
// bf16 3-term split: C = Ah*Bh + Ah*Bl + Al*Bh, fp32 accumulate.
__global__ void __launch_bounds__(256, 2) k_gemm(const float* __restrict__ feat,
                                                 const float* __restrict__ attn_l,
                                                 const float* __restrict__ attn_r) {
    extern __shared__ __nv_bfloat16 smem[];
    __nv_bfloat16* sAh = smem;                       // 64 x PITCH
    __nv_bfloat16* sAl = sAh + 64 * PITCH;
    __nv_bfloat16* sBh = sAl + 64 * PITCH;           // 128 x PITCH
    __nv_bfloat16* sBl = sBh + 128 * PITCH;
    __shared__ float sEl[4][64];
    __shared__ float sEr[4][64];

    const int t = threadIdx.x;
    const int row0 = blockIdx.y * 64;
    const int nblk = blockIdx.x;

    // ---- A tile (fp32 -> bf16 hi/lo): 64x128 = 2048 float4, 256 thr x 8 ----
#pragma unroll
    for (int i = 0; i < 8; i++) {
        int id = t + i * 256;             // 0..2047
        int r = id >> 5;                  // 0..63
        int q = (id & 31) << 2;           // 0..124
        float4 v = make_float4(0.f, 0.f, 0.f, 0.f);
        if (row0 + r < NN)
            v = *(const float4*)&feat[(size_t)(row0 + r) * 128 + q];
        __nv_bfloat16 h0 = __float2bfloat16(v.x);
        __nv_bfloat16 h1 = __float2bfloat16(v.y);
        __nv_bfloat16 h2 = __float2bfloat16(v.z);
        __nv_bfloat16 h3 = __float2bfloat16(v.w);
        __nv_bfloat16 l0 = __float2bfloat16(v.x - __bfloat162float(h0));
        __nv_bfloat16 l1 = __float2bfloat16(v.y - __bfloat162float(h1));
        __nv_bfloat16 l2 = __float2bfloat16(v.z - __bfloat162float(h2));
        __nv_bfloat16 l3 = __float2bfloat16(v.w - __bfloat162float(h3));
        __nv_bfloat162* ph = (__nv_bfloat162*)&sAh[r * PITCH + q];
        ph[0] = __nv_bfloat162(h0, h1); ph[1] = __nv_bfloat162(h2, h3);
        __nv_bfloat162* pl = (__nv_bfloat162*)&sAl[r * PITCH + q];
        pl[0] = __nv_bfloat162(l0, l1); pl[1] = __nv_bfloat162(l2, l3);
    }
    // ---- B tile (pre-split bf16): 128 rows of this W block -----------------
#pragma unroll
    for (int i = 0; i < 16; i++) {
        int id = t + i * 256;             // 0..4095
        int r = id >> 5;                  // 0..127
        int q = (id & 31) << 2;
        *(uint2*)&sBh[r * PITCH + q] = *(const uint2*)&g_Wbh[(nblk * 128 + r) * 128 + q];
        *(uint2*)&sBl[r * PITCH + q] = *(const uint2*)&g_Wbl[(nblk * 128 + r) * 128 + q];
    }
    __syncthreads();

    // ---- warp tiling: 8 warps in 2(M) x 4(N); each 32(M) x 32(N) ----
    const int wid = t >> 5, lane = t & 31;
    const int m0w = (wid >> 2) * 32;
    const int n0w = (wid & 3) * 32;

    float acc[2][4][4];
#pragma unroll
    for (int mt = 0; mt < 2; mt++)
#pragma unroll
        for (int nt = 0; nt < 4; nt++)
#pragma unroll
            for (int f = 0; f < 4; f++) acc[mt][nt][f] = 0.f;

#pragma unroll
    for (int kc = 0; kc < 8; kc++) {
        const int k0 = kc * 16;
        uint32_t a_h[2][4], a_l[2][4];
#pragma unroll
        for (int mt = 0; mt < 2; mt++) {
            int r = m0w + mt * 16 + (lane & 7) + ((lane >> 3) & 1) * 8;
            int c = k0 + (lane >> 4) * 8;
            ldsm4(a_h[mt], &sAh[r * PITCH + c]);
            ldsm4(a_l[mt], &sAl[r * PITCH + c]);
        }
        uint32_t b_h[2][4], b_l[2][4];
#pragma unroll
        for (int np = 0; np < 2; np++) {
            int r = n0w + np * 16 + (lane & 7) + (lane >> 4) * 8;
            int c = k0 + ((lane >> 3) & 1) * 8;
            ldsm4(b_h[np], &sBh[r * PITCH + c]);
            ldsm4(b_l[np], &sBl[r * PITCH + c]);
        }
#pragma unroll
        for (int mt = 0; mt < 2; mt++)
#pragma unroll
            for (int nt = 0; nt < 4; nt++) {
                uint32_t bh0 = b_h[nt >> 1][(nt & 1) * 2];
                uint32_t bh1 = b_h[nt >> 1][(nt & 1) * 2 + 1];
                uint32_t bl0 = b_l[nt >> 1][(nt & 1) * 2];
                uint32_t bl1 = b_l[nt >> 1][(nt & 1) * 2 + 1];
                mma_bf16(acc[mt][nt], a_h[mt], bh0, bh1);
                mma_bf16(acc[mt][nt], a_h[mt], bl0, bl1);
                mma_bf16(acc[mt][nt], a_l[mt], bh0, bh1);
            }
    }

    // ---- epilogue: bias + store; fused el/er for nblk==0 --------------------
    const int g = lane >> 2, c2 = (lane & 3) * 2;
    const int head = wid & 3;      // this warp's 32 cols = one head
    float elp[2][2] = {{0.f, 0.f}, {0.f, 0.f}};
    float erp[2][2] = {{0.f, 0.f}, {0.f, 0.f}};
#pragma unroll
    for (int mt = 0; mt < 2; mt++) {
        int rbase = row0 + m0w + mt * 16 + g;
#pragma unroll
        for (int nt = 0; nt < 4; nt++) {
            int col = n0w + nt * 8 + c2;
            float b0 = g_bcat[nblk * 128 + col];
            float b1 = g_bcat[nblk * 128 + col + 1];
            float f0 = acc[mt][nt][0] + b0, f1 = acc[mt][nt][1] + b1;
            float f2 = acc[mt][nt][2] + b0, f3 = acc[mt][nt][3] + b1;
            if (nblk == 0) {
                // featsrc in fp16 + attention partial dots
                if (rbase < NN)
                    *(__half2*)&g_fsh[(size_t)rbase * 128 + col] = __floats2half2_rn(f0, f1);
                if (rbase + 8 < NN)
                    *(__half2*)&g_fsh[(size_t)(rbase + 8) * 128 + col] = __floats2half2_rn(f2, f3);
                float al0 = attn_l[col], al1 = attn_l[col + 1];
                float ar0 = attn_r[col], ar1 = attn_r[col + 1];
                elp[mt][0] += f0 * al0 + f1 * al1;
                elp[mt][1] += f2 * al0 + f3 * al1;
                erp[mt][0] += f0 * ar0 + f1 * ar1;
                erp[mt][1] += f2 * ar0 + f3 * ar1;
            } else {
                if (rbase < NN)
                    *(float2*)&g_skip[(size_t)rbase * 128 + col] = make_float2(f0, f1);
                if (rbase + 8 < NN)
                    *(float2*)&g_skip[(size_t)(rbase + 8) * 128 + col] = make_float2(f2, f3);
            }
        }
    }
    if (nblk == 0) {
        // reduce across the lane quad (lanes sharing g)
#pragma unroll
        for (int mt = 0; mt < 2; mt++)
#pragma unroll
            for (int hf = 0; hf < 2; hf++) {
                elp[mt][hf] += __shfl_xor_sync(0xffffffffu, elp[mt][hf], 1);
                elp[mt][hf] += __shfl_xor_sync(0xffffffffu, elp[mt][hf], 2);
                erp[mt][hf] += __shfl_xor_sync(0xffffffffu, erp[mt][hf], 1);
                erp[mt][hf] += __shfl_xor_sync(0xffffffffu, erp[mt][hf], 2);
            }
        if ((lane & 3) == 0) {
#pragma unroll
            for (int mt = 0; mt < 2; mt++)
#pragma unroll
                for (int hf = 0; hf < 2; hf++) {
                    int lr = m0w + mt * 16 + g + hf * 8;   // 0..63
                    sEl[head][lr] = elp[mt][hf];
                    sEr[head][lr] = erp[mt][hf];
                }
        }
        __syncthreads();
        int lr = t >> 2, h = t & 3;   // 64 rows x 4 heads
        if (row0 + lr < NN) {
            g_el[(row0 + lr) * 4 + h] = sEl[h][lr];
            g_er[(row0 + lr) * 4 + h] = sEr[h][lr];
        }
    }
}

// ---------------- K4c: add block offsets -------------------------------------
__global__ void k_scan3() {
    int i = blockIdx.x * 1024 + threadIdx.x;
    if (i < NN) g_rowptr[i] += g_boff[blockIdx.x];
}

// ---------------- K5: fill CSR (atomics consume g_rowptr in place) ----------
// After this kernel, g_rowptr[d] == original rowptr[d+1] (end pointer).
__global__ void k_fill(const int* __restrict__ src, const int* __restrict__ dst) {
    int i = blockIdx.x * blockDim.x + threadIdx.x;
    if (i < EE) {
        int slot = atomicAdd(&g_rowptr[dst[i]], 1);
        g_csrc[slot] = src[i];
    }
}

// ---------------- K6: per-node softmax + aggregate + gate + LN + PReLU ------
// Shifted CSR read: start = rowptr[n-1] (or 0), end = rowptr[n].
// fp16 gather halves L2 traffic; exp without max-subtract (logits O(5)).
__global__ void k_node(const float* __restrict__ W_gate, const float* __restrict__ b_gate,
                       const float* __restrict__ ln_g, const float* __restrict__ ln_b,
                       const float* __restrict__ prelu_a, float* __restrict__ out) {
    int gid = blockIdx.x * blockDim.x + threadIdx.x;
    int n = gid >> 5;
    int lane = threadIdx.x & 31;
    if (n >= NN) return;
    const int h = lane >> 3;

    int start = (n == 0) ? 0 : g_rowptr[n - 1];
    int end = g_rowptr[n];
    int deg = end - start;
    float erh = g_er[n * 4 + h];

    float4 acc = make_float4(0.f, 0.f, 0.f, 0.f);
    float sumex = 0.f;
    int k = start;
    for (; k + 3 < end; k += 4) {
        int s0 = g_csrc[k], s1 = g_csrc[k + 1];
        int s2 = g_csrc[k + 2], s3 = g_csrc[k + 3];
        float e0 = g_el[s0 * 4 + h] + erh;
        float e1 = g_el[s1 * 4 + h] + erh;
        float e2 = g_el[s2 * 4 + h] + erh;
        float e3 = g_el[s3 * 4 + h] + erh;
        uint2 u0 = *(const uint2*)&g_fsh[(size_t)s0 * 128 + 4 * lane];
        uint2 u1 = *(const uint2*)&g_fsh[(size_t)s1 * 128 + 4 * lane];
        uint2 u2 = *(const uint2*)&g_fsh[(size_t)s2 * 128 + 4 * lane];
        uint2 u3 = *(const uint2*)&g_fsh[(size_t)s3 * 128 + 4 * lane];
        e0 = (e0 >= 0.f) ? e0 : 0.2f * e0;
        e1 = (e1 >= 0.f) ? e1 : 0.2f * e1;
        e2 = (e2 >= 0.f) ? e2 : 0.2f * e2;
        e3 = (e3 >= 0.f) ? e3 : 0.2f * e3;
        float x0 = __expf(e0), x1 = __expf(e1), x2 = __expf(e2), x3 = __expf(e3);
        sumex += x0 + x1 + x2 + x3;
        float2 a0 = __half22float2(*(__half2*)&u0.x), b0 = __half22float2(*(__half2*)&u0.y);
        float2 a1 = __half22float2(*(__half2*)&u1.x), b1 = __half22float2(*(__half2*)&u1.y);
        float2 a2 = __half22float2(*(__half2*)&u2.x), b2 = __half22float2(*(__half2*)&u2.y);
        float2 a3 = __half22float2(*(__half2*)&u3.x), b3 = __half22float2(*(__half2*)&u3.y);
        acc.x += x0 * a0.x + x1 * a1.x + x2 * a2.x + x3 * a3.x;
        acc.y += x0 * a0.y + x1 * a1.y + x2 * a2.y + x3 * a3.y;
        acc.z += x0 * b0.x + x1 * b1.x + x2 * b2.x + x3 * b3.x;
        acc.w += x0 * b0.y + x1 * b1.y + x2 * b2.y + x3 * b3.y;
    }
    for (; k < end; k++) {
        int s = g_csrc[k];
        float e = g_el[s * 4 + h] + erh;
        e = (e >= 0.f) ? e : 0.2f * e;
        float ex = __expf(e);
        sumex += ex;
        uint2 u = *(const uint2*)&g_fsh[(size_t)s * 128 + 4 * lane];
        float2 a = __half22float2(*(__half2*)&u.x), b = __half22float2(*(__half2*)&u.y);
        acc.x += ex * a.x; acc.y += ex * a.y;
        acc.z += ex * b.x; acc.w += ex * b.y;
    }
    float4 rst;
    if (deg > 0) {
        float inv = 1.0f / sumex;
        rst = make_float4(acc.x * inv, acc.y * inv, acc.z * inv, acc.w * inv);
    } else {
        rst = make_float4(0.f, 0.f, 0.f, 0.f);
    }

    float4 sk = *(const float4*)&g_skip[(size_t)n * 128 + 4 * lane];
    float4 w1 = *(const float4*)&W_gate[4 * lane];
    float4 w2 = *(const float4*)&W_gate[128 + 4 * lane];
    float4 w3 = *(const float4*)&W_gate[256 + 4 * lane];
    float gacc = rst.x * w1.x + rst.y * w1.y + rst.z * w1.z + rst.w * w1.w
               + sk.x * w2.x + sk.y * w2.y + sk.z * w2.z + sk.w * w2.w
               + (rst.x - sk.x) * w3.x + (rst.y - sk.y) * w3.y
               + (rst.z - sk.z) * w3.z + (rst.w - sk.w) * w3.w;
#pragma unroll
    for (int off = 16; off >= 1; off >>= 1)
        gacc += __shfl_xor_sync(0xffffffffu, gacc, off);
    float gate = 1.0f / (1.0f + __expf(-(gacc + b_gate[0])));
    float4 x = make_float4(gate * rst.x + (1.f - gate) * sk.x,
                           gate * rst.y + (1.f - gate) * sk.y,
                           gate * rst.z + (1.f - gate) * sk.z,
                           gate * rst.w + (1.f - gate) * sk.w);

    float s1 = x.x + x.y + x.z + x.w;
    float s2 = x.x * x.x + x.y * x.y + x.z * x.z + x.w * x.w;
#pragma unroll
    for (int off = 16; off >= 1; off >>= 1) {
        s1 += __shfl_xor_sync(0xffffffffu, s1, off);
        s2 += __shfl_xor_sync(0xffffffffu, s2, off);
    }
    float mean = s1 * (1.0f / 128.0f);
    float var = s2 * (1.0f / 128.0f) - mean * mean;
    float inv = rsqrtf(var + 1e-5f);
    float4 g4 = *(const float4*)&ln_g[4 * lane];
    float4 b4 = *(const float4*)&ln_b[4 * lane];
    float alpha = prelu_a[0];
    float y0 = (x.x - mean) * inv * g4.x + b4.x;
    float y1 = (x.y - mean) * inv * g4.y + b4.y;
    float y2 = (x.z - mean) * inv * g4.z + b4.z;
    float y3 = (x.w - mean) * inv * g4.w + b4.w;
    y0 = (y0 >= 0.f) ? y0 : alpha * y0;
    y1 = (y1 >= 0.f) ? y1 : alpha * y1;
    y2 = (y2 >= 0.f) ? y2 : alpha * y2;
    y3 = (y3 >= 0.f) ? y3 : alpha * y3;
    *(float4*)&out[(size_t)n * 128 + 4 * lane] = make_float4(y0, y1, y2, y3);
}

// ---------------- launcher ---------------------------------------------------
extern "C" void kernel_launch(void* const* d_in, const int* in_sizes, int n_in,
                              void* d_out, int out_size) {
    const float* feat    = (const float*)d_in[0];
    const int*   src     = (const int*)d_in[1];
    const int*   dst     = (const int*)d_in[2];
    const float* W_src   = (const float*)d_in[3];
    const float* b_src   = (const float*)d_in[4];
    const float* attn_l  = (const float*)d_in[5];
    const float* attn_r  = (const float*)d_in[6];
    const float* W_skip  = (const float*)d_in[7];
    const float* b_skip  = (const float*)d_in[8];
    const float* W_gate  = (const float*)d_in[9];
    const float* b_gate  = (const float*)d_in[10];
    const float* ln_g    = (const float*)d_in[11];
    const float* ln_b    = (const float*)d_in[12];
    const float* prelu_a = (const float*)d_in[13];
    float* out = (float*)d_out;

    // smem: (64 + 64 + 128 + 128) * PITCH * 2B = 104448
    const int GEMM_SMEM = (64 + 64 + 128 + 128) * PITCH * (int)sizeof(__nv_bfloat16);
    static int smem_set = 0;
    if (!smem_set) {
        cudaFuncSetAttribute(k_gemm, cudaFuncAttributeMaxDynamicSharedMemorySize, GEMM_SMEM);
        smem_set = 1;
    }

    // k_gemm kept as the 4th launch (the one ncu captures).
    k_prepdeg<<<(EE + 511) / 512, 512>>>(W_src, b_src, W_skip, b_skip, dst);
    k_scan1<<<98, 1024>>>();
    k_scan2<<<1, 128>>>();
    k_gemm<<<dim3(2, (NN + 63) / 64), 256, GEMM_SMEM>>>(feat, attn_l, attn_r);
    k_scan3<<<98, 1024>>>();
    k_fill<<<(EE + 255) / 256, 256>>>(src, dst);
    k_node<<<(NN * 32 + 255) / 256, 256>>>(W_gate, b_gate, ln_g, ln_b, prelu_a, out);
}

// round 11
// speedup vs baseline: 1.4395x; 1.2783x over previous
#include <cuda_runtime.h>
#include <cuda_fp16.h>
#include <stdint.h>

#define NN 100000
#define EE 800000
#define HD 128
#define PITCH 136   // padded smem row (fp16 elems) -> conflict-free LDSM

// ---------------- scratch (static device memory; no allocs) ----------------
__device__ __half g_fsh[NN * HD];    // featsrc in fp16 (gather payload)
__device__ float g_skip[NN * HD];
__device__ float g_el[NN * 4];
__device__ float g_er[NN * 4];
__device__ int   g_deg[NN];          // zero-init; k_scan1 re-zeroes after read
__device__ int   g_rowptr[NN];       // rebuilt every replay; consumed by fill
__device__ int   g_csrc[EE];
__device__ __half g_Wh[256 * 128];   // [W_src; W_skip] in fp16
__device__ float g_bcat[256];
__device__ int   g_bsum[128];
__device__ int   g_boff[128];

// ---------------- mma helpers -----------------------------------------------
__device__ __forceinline__ void ldsm4(uint32_t* d, const void* p) {
    uint32_t a = (uint32_t)__cvta_generic_to_shared(p);
    asm volatile("ldmatrix.sync.aligned.m8n8.x4.shared.b16 {%0,%1,%2,%3}, [%4];"
                 : "=r"(d[0]), "=r"(d[1]), "=r"(d[2]), "=r"(d[3]) : "r"(a));
}

__device__ __forceinline__ void mma_fp16(float* c, const uint32_t* a,
                                         uint32_t b0, uint32_t b1) {
    asm volatile(
        "mma.sync.aligned.m16n8k16.row.col.f32.f16.f16.f32 "
        "{%0,%1,%2,%3}, {%4,%5,%6,%7}, {%8,%9}, {%0,%1,%2,%3};"
        : "+f"(c[0]), "+f"(c[1]), "+f"(c[2]), "+f"(c[3])
        : "r"(a[0]), "r"(a[1]), "r"(a[2]), "r"(a[3]), "r"(b0), "r"(b1));
}

// ---------------- K0: prep (W -> fp16) + degree count, fused ----------------
__global__ void k_prepdeg(const float* __restrict__ W_src, const float* __restrict__ b_src,
                          const float* __restrict__ W_skip, const float* __restrict__ b_skip,
                          const int* __restrict__ dst) {
    int i = blockIdx.x * blockDim.x + threadIdx.x;
    if (i < 128 * 128) {
        g_Wh[i] = __float2half_rn(W_src[i]);
        g_Wh[16384 + i] = __float2half_rn(W_skip[i]);
    }
    if (i < 128) {
        g_bcat[i] = b_src[i];
        g_bcat[128 + i] = b_skip[i];
    }
    if (i < EE) atomicAdd(&g_deg[dst[i]], 1);
}

// ---------------- K4a: per-block scan; zeroes g_deg --------------------------
__global__ void k_scan1() {
    __shared__ int wsum[32];
    const int t = threadIdx.x;
    const int b = blockIdx.x;
    const int lane = t & 31, w = t >> 5;
    const int i = b * 1024 + t;
    int v = (i < NN) ? g_deg[i] : 0;
    if (i < NN) g_deg[i] = 0;
    int x = v;
#pragma unroll
    for (int off = 1; off < 32; off <<= 1) {
        int y = __shfl_up_sync(0xffffffffu, x, off);
        if (lane >= off) x += y;
    }
    if (lane == 31) wsum[w] = x;
    __syncthreads();
    if (w == 0) {
        int y = wsum[lane];
#pragma unroll
        for (int off = 1; off < 32; off <<= 1) {
            int z = __shfl_up_sync(0xffffffffu, y, off);
            if (lane >= off) y += z;
        }
        wsum[lane] = y;
    }
    __syncthreads();
    int incl = x + (w > 0 ? wsum[w - 1] : 0);
    if (i < NN) g_rowptr[i] = incl - v;   // exclusive within block
    if (t == 1023) g_bsum[b] = incl;
}

// ---------------- K4b: scan of 98 block sums ---------------------------------
__global__ void k_scan2() {
    __shared__ int wsum[4];
    const int t = threadIdx.x;  // 128
    const int lane = t & 31, w = t >> 5;
    const int NB = 98;
    int v = (t < NB) ? g_bsum[t] : 0;
    int x = v;
#pragma unroll
    for (int off = 1; off < 32; off <<= 1) {
        int y = __shfl_up_sync(0xffffffffu, x, off);
        if (lane >= off) x += y;
    }
    if (lane == 31) wsum[w] = x;
    __syncthreads();
    int carry = 0;
#pragma unroll
    for (int k = 0; k < 4; k++) if (k < w) carry += wsum[k];
    int incl = x + carry;
    if (t < NB) g_boff[t] = incl - v;
}

// ---------------- K1: single-term fp16 mma GEMM, M=64 x N=128 per CTA -------
// grid (2, 1563): x=0 -> featsrc(fp16) + fused el/er, x=1 -> skip (fp32).
// Adjacent blockIdx.x pair shares the A tile -> 2nd read hits L2.
__global__ void __launch_bounds__(256, 3) k_gemm(const float* __restrict__ feat,
                                                 const float* __restrict__ attn_l,
                                                 const float* __restrict__ attn_r) {
    extern __shared__ __half smem[];
    __half* sA = smem;                      // 64 x PITCH
    __half* sB = sA + 64 * PITCH;           // 128 x PITCH
    __shared__ float sEl[4][64];
    __shared__ float sEr[4][64];

    const int t = threadIdx.x;
    const int row0 = blockIdx.y * 64;
    const int nblk = blockIdx.x;

    // ---- A tile (fp32 -> fp16): 64x128 = 2048 float4, 256 thr x 8 ----
#pragma unroll
    for (int i = 0; i < 8; i++) {
        int id = t + i * 256;             // 0..2047
        int r = id >> 5;                  // 0..63
        int q = (id & 31) << 2;           // 0..124
        float4 v = make_float4(0.f, 0.f, 0.f, 0.f);
        if (row0 + r < NN)
            v = *(const float4*)&feat[(size_t)(row0 + r) * 128 + q];
        __half2* p = (__half2*)&sA[r * PITCH + q];
        p[0] = __floats2half2_rn(v.x, v.y);
        p[1] = __floats2half2_rn(v.z, v.w);
    }
    // ---- B tile (pre-converted fp16): 128 rows of this W block -------------
#pragma unroll
    for (int i = 0; i < 16; i++) {
        int id = t + i * 256;             // 0..4095
        int r = id >> 5;                  // 0..127
        int q = (id & 31) << 2;
        *(uint2*)&sB[r * PITCH + q] = *(const uint2*)&g_Wh[(nblk * 128 + r) * 128 + q];
    }
    __syncthreads();

    // ---- warp tiling: 8 warps in 2(M) x 4(N); each 32(M) x 32(N) ----
    const int wid = t >> 5, lane = t & 31;
    const int m0w = (wid >> 2) * 32;
    const int n0w = (wid & 3) * 32;

    float acc[2][4][4];
#pragma unroll
    for (int mt = 0; mt < 2; mt++)
#pragma unroll
        for (int nt = 0; nt < 4; nt++)
#pragma unroll
            for (int f = 0; f < 4; f++) acc[mt][nt][f] = 0.f;

#pragma unroll
    for (int kc = 0; kc < 8; kc++) {
        const int k0 = kc * 16;
        uint32_t a[2][4];
#pragma unroll
        for (int mt = 0; mt < 2; mt++) {
            int r = m0w + mt * 16 + (lane & 7) + ((lane >> 3) & 1) * 8;
            int c = k0 + (lane >> 4) * 8;
            ldsm4(a[mt], &sA[r * PITCH + c]);
        }
        uint32_t b[2][4];
#pragma unroll
        for (int np = 0; np < 2; np++) {
            int r = n0w + np * 16 + (lane & 7) + (lane >> 4) * 8;
            int c = k0 + ((lane >> 3) & 1) * 8;
            ldsm4(b[np], &sB[r * PITCH + c]);
        }
#pragma unroll
        for (int mt = 0; mt < 2; mt++)
#pragma unroll
            for (int nt = 0; nt < 4; nt++)
                mma_fp16(acc[mt][nt], a[mt],
                         b[nt >> 1][(nt & 1) * 2], b[nt >> 1][(nt & 1) * 2 + 1]);
    }

    // ---- epilogue: bias + store; fused el/er for nblk==0 --------------------
    const int g = lane >> 2, c2 = (lane & 3) * 2;
    const int head = wid & 3;      // this warp's 32 cols = one head
    float elp[2][2] = {{0.f, 0.f}, {0.f, 0.f}};
    float erp[2][2] = {{0.f, 0.f}, {0.f, 0.f}};
#pragma unroll
    for (int mt = 0; mt < 2; mt++) {
        int rbase = row0 + m0w + mt * 16 + g;
#pragma unroll
        for (int nt = 0; nt < 4; nt++) {
            int col = n0w + nt * 8 + c2;
            float b0 = g_bcat[nblk * 128 + col];
            float b1 = g_bcat[nblk * 128 + col + 1];
            float f0 = acc[mt][nt][0] + b0, f1 = acc[mt][nt][1] + b1;
            float f2 = acc[mt][nt][2] + b0, f3 = acc[mt][nt][3] + b1;
            if (nblk == 0) {
                if (rbase < NN)
                    *(__half2*)&g_fsh[(size_t)rbase * 128 + col] = __floats2half2_rn(f0, f1);
                if (rbase + 8 < NN)
                    *(__half2*)&g_fsh[(size_t)(rbase + 8) * 128 + col] = __floats2half2_rn(f2, f3);
                float al0 = attn_l[col], al1 = attn_l[col + 1];
                float ar0 = attn_r[col], ar1 = attn_r[col + 1];
                elp[mt][0] += f0 * al0 + f1 * al1;
                elp[mt][1] += f2 * al0 + f3 * al1;
                erp[mt][0] += f0 * ar0 + f1 * ar1;
                erp[mt][1] += f2 * ar0 + f3 * ar1;
            } else {
                if (rbase < NN)
                    *(float2*)&g_skip[(size_t)rbase * 128 + col] = make_float2(f0, f1);
                if (rbase + 8 < NN)
                    *(float2*)&g_skip[(size_t)(rbase + 8) * 128 + col] = make_float2(f2, f3);
            }
        }
    }
    if (nblk == 0) {
        // reduce across the lane quad (lanes sharing g)
#pragma unroll
        for (int mt = 0; mt < 2; mt++)
#pragma unroll
            for (int hf = 0; hf < 2; hf++) {
                elp[mt][hf] += __shfl_xor_sync(0xffffffffu, elp[mt][hf], 1);
                elp[mt][hf] += __shfl_xor_sync(0xffffffffu, elp[mt][hf], 2);
                erp[mt][hf] += __shfl_xor_sync(0xffffffffu, erp[mt][hf], 1);
                erp[mt][hf] += __shfl_xor_sync(0xffffffffu, erp[mt][hf], 2);
            }
        if ((lane & 3) == 0) {
#pragma unroll
            for (int mt = 0; mt < 2; mt++)
#pragma unroll
                for (int hf = 0; hf < 2; hf++) {
                    int lr = m0w + mt * 16 + g + hf * 8;   // 0..63
                    sEl[head][lr] = elp[mt][hf];
                    sEr[head][lr] = erp[mt][hf];
                }
        }
        __syncthreads();
        int lr = t >> 2, h = t & 3;   // 64 rows x 4 heads
        if (row0 + lr < NN) {
            g_el[(row0 + lr) * 4 + h] = sEl[h][lr];
            g_er[(row0 + lr) * 4 + h] = sEr[h][lr];
        }
    }
}

// ---------------- K4c: add block offsets -------------------------------------
__global__ void k_scan3() {
    int i = blockIdx.x * 1024 + threadIdx.x;
    if (i < NN) g_rowptr[i] += g_boff[blockIdx.x];
}

// ---------------- K5: fill CSR (atomics consume g_rowptr in place) ----------
__global__ void k_fill(const int* __restrict__ src, const int* __restrict__ dst) {
    int i = blockIdx.x * blockDim.x + threadIdx.x;
    if (i < EE) {
        int slot = atomicAdd(&g_rowptr[dst[i]], 1);
        g_csrc[slot] = src[i];
    }
}

// ---------------- K6: per-node softmax + aggregate + gate + LN + PReLU ------
__global__ void k_node(const float* __restrict__ W_gate, const float* __restrict__ b_gate,
                       const float* __restrict__ ln_g, const float* __restrict__ ln_b,
                       const float* __restrict__ prelu_a, float* __restrict__ out) {
    int gid = blockIdx.x * blockDim.x + threadIdx.x;
    int n = gid >> 5;
    int lane = threadIdx.x & 31;
    if (n >= NN) return;
    const int h = lane >> 3;

    int start = (n == 0) ? 0 : g_rowptr[n - 1];
    int end = g_rowptr[n];
    int deg = end - start;
    float erh = g_er[n * 4 + h];

    float4 acc = make_float4(0.f, 0.f, 0.f, 0.f);
    float sumex = 0.f;
    int k = start;
    for (; k + 3 < end; k += 4) {
        int s0 = g_csrc[k], s1 = g_csrc[k + 1];
        int s2 = g_csrc[k + 2], s3 = g_csrc[k + 3];
        float e0 = g_el[s0 * 4 + h] + erh;
        float e1 = g_el[s1 * 4 + h] + erh;
        float e2 = g_el[s2 * 4 + h] + erh;
        float e3 = g_el[s3 * 4 + h] + erh;
        uint2 u0 = *(const uint2*)&g_fsh[(size_t)s0 * 128 + 4 * lane];
        uint2 u1 = *(const uint2*)&g_fsh[(size_t)s1 * 128 + 4 * lane];
        uint2 u2 = *(const uint2*)&g_fsh[(size_t)s2 * 128 + 4 * lane];
        uint2 u3 = *(const uint2*)&g_fsh[(size_t)s3 * 128 + 4 * lane];
        e0 = (e0 >= 0.f) ? e0 : 0.2f * e0;
        e1 = (e1 >= 0.f) ? e1 : 0.2f * e1;
        e2 = (e2 >= 0.f) ? e2 : 0.2f * e2;
        e3 = (e3 >= 0.f) ? e3 : 0.2f * e3;
        float x0 = __expf(e0), x1 = __expf(e1), x2 = __expf(e2), x3 = __expf(e3);
        sumex += x0 + x1 + x2 + x3;
        float2 a0 = __half22float2(*(__half2*)&u0.x), b0 = __half22float2(*(__half2*)&u0.y);
        float2 a1 = __half22float2(*(__half2*)&u1.x), b1 = __half22float2(*(__half2*)&u1.y);
        float2 a2 = __half22float2(*(__half2*)&u2.x), b2 = __half22float2(*(__half2*)&u2.y);
        float2 a3 = __half22float2(*(__half2*)&u3.x), b3 = __half22float2(*(__half2*)&u3.y);
        acc.x += x0 * a0.x + x1 * a1.x + x2 * a2.x + x3 * a3.x;
        acc.y += x0 * a0.y + x1 * a1.y + x2 * a2.y + x3 * a3.y;
        acc.z += x0 * b0.x + x1 * b1.x + x2 * b2.x + x3 * b3.x;
        acc.w += x0 * b0.y + x1 * b1.y + x2 * b2.y + x3 * b3.y;
    }
    for (; k < end; k++) {
        int s = g_csrc[k];
        float e = g_el[s * 4 + h] + erh;
        e = (e >= 0.f) ? e : 0.2f * e;
        float ex = __expf(e);
        sumex += ex;
        uint2 u = *(const uint2*)&g_fsh[(size_t)s * 128 + 4 * lane];
        float2 a = __half22float2(*(__half2*)&u.x), b = __half22float2(*(__half2*)&u.y);
        acc.x += ex * a.x; acc.y += ex * a.y;
        acc.z += ex * b.x; acc.w += ex * b.y;
    }
    float4 rst;
    if (deg > 0) {
        float inv = 1.0f / sumex;
        rst = make_float4(acc.x * inv, acc.y * inv, acc.z * inv, acc.w * inv);
    } else {
        rst = make_float4(0.f, 0.f, 0.f, 0.f);
    }

    float4 sk = *(const float4*)&g_skip[(size_t)n * 128 + 4 * lane];
    float4 w1 = *(const float4*)&W_gate[4 * lane];
    float4 w2 = *(const float4*)&W_gate[128 + 4 * lane];
    float4 w3 = *(const float4*)&W_gate[256 + 4 * lane];
    float gacc = rst.x * w1.x + rst.y * w1.y + rst.z * w1.z + rst.w * w1.w
               + sk.x * w2.x + sk.y * w2.y + sk.z * w2.z + sk.w * w2.w
               + (rst.x - sk.x) * w3.x + (rst.y - sk.y) * w3.y
               + (rst.z - sk.z) * w3.z + (rst.w - sk.w) * w3.w;
#pragma unroll
    for (int off = 16; off >= 1; off >>= 1)
        gacc += __shfl_xor_sync(0xffffffffu, gacc, off);
    float gate = 1.0f / (1.0f + __expf(-(gacc + b_gate[0])));
    float4 x = make_float4(gate * rst.x + (1.f - gate) * sk.x,
                           gate * rst.y + (1.f - gate) * sk.y,
                           gate * rst.z + (1.f - gate) * sk.z,
                           gate * rst.w + (1.f - gate) * sk.w);

    float s1 = x.x + x.y + x.z + x.w;
    float s2 = x.x * x.x + x.y * x.y + x.z * x.z + x.w * x.w;
#pragma unroll
    for (int off = 16; off >= 1; off >>= 1) {
        s1 += __shfl_xor_sync(0xffffffffu, s1, off);
        s2 += __shfl_xor_sync(0xffffffffu, s2, off);
    }
    float mean = s1 * (1.0f / 128.0f);
    float var = s2 * (1.0f / 128.0f) - mean * mean;
    float inv = rsqrtf(var + 1e-5f);
    float4 g4 = *(const float4*)&ln_g[4 * lane];
    float4 b4 = *(const float4*)&ln_b[4 * lane];
    float alpha = prelu_a[0];
    float y0 = (x.x - mean) * inv * g4.x + b4.x;
    float y1 = (x.y - mean) * inv * g4.y + b4.y;
    float y2 = (x.z - mean) * inv * g4.z + b4.z;
    float y3 = (x.w - mean) * inv * g4.w + b4.w;
    y0 = (y0 >= 0.f) ? y0 : alpha * y0;
    y1 = (y1 >= 0.f) ? y1 : alpha * y1;
    y2 = (y2 >= 0.f) ? y2 : alpha * y2;
    y3 = (y3 >= 0.f) ? y3 : alpha * y3;
    *(float4*)&out[(size_t)n * 128 + 4 * lane] = make_float4(y0, y1, y2, y3);
}

// ---------------- launcher ---------------------------------------------------
extern "C" void kernel_launch(void* const* d_in, const int* in_sizes, int n_in,
                              void* d_out, int out_size) {
    const float* feat    = (const float*)d_in[0];
    const int*   src     = (const int*)d_in[1];
    const int*   dst     = (const int*)d_in[2];
    const float* W_src   = (const float*)d_in[3];
    const float* b_src   = (const float*)d_in[4];
    const float* attn_l  = (const float*)d_in[5];
    const float* attn_r  = (const float*)d_in[6];
    const float* W_skip  = (const float*)d_in[7];
    const float* b_skip  = (const float*)d_in[8];
    const float* W_gate  = (const float*)d_in[9];
    const float* b_gate  = (const float*)d_in[10];
    const float* ln_g    = (const float*)d_in[11];
    const float* ln_b    = (const float*)d_in[12];
    const float* prelu_a = (const float*)d_in[13];
    float* out = (float*)d_out;

    // smem: (64 + 128) * PITCH * 2B = 52224
    const int GEMM_SMEM = (64 + 128) * PITCH * (int)sizeof(__half);
    static int smem_set = 0;
    if (!smem_set) {
        cudaFuncSetAttribute(k_gemm, cudaFuncAttributeMaxDynamicSharedMemorySize, GEMM_SMEM);
        smem_set = 1;
    }

    // k_gemm kept as the 4th launch (the one ncu captures).
    k_prepdeg<<<(EE + 511) / 512, 512>>>(W_src, b_src, W_skip, b_skip, dst);
    k_scan1<<<98, 1024>>>();
    k_scan2<<<1, 128>>>();
    k_gemm<<<dim3(2, (NN + 63) / 64), 256, GEMM_SMEM>>>(feat, attn_l, attn_r);
    k_scan3<<<98, 1024>>>();
    k_fill<<<(EE + 255) / 256, 256>>>(src, dst);
    k_node<<<(NN * 32 + 255) / 256, 256>>>(W_gate, b_gate, ln_g, ln_b, prelu_a, out);
}

// round 12
// speedup vs baseline: 1.4402x; 1.0005x over previous
#include <cuda_runtime.h>
#include <cuda_fp16.h>
#include <stdint.h>

#define NN 100000
#define EE 800000
#define HD 128
#define PITCH 136   // padded smem row (fp16 elems) -> conflict-free LDSM

#define GEMM_BLKS 3126            // 1563 row-blocks x 2 (featsrc/skip)
#define DEG_BLKS  3125            // 800000 / 256
#define FAT_BLKS  (GEMM_BLKS + DEG_BLKS)

// ---------------- scratch (static device memory; no allocs) ----------------
__device__ __half g_fsh[NN * HD];    // featsrc in fp16 (gather payload)
__device__ float g_skip[NN * HD];
__device__ float g_el[NN * 4];
__device__ float g_er[NN * 4];
__device__ int   g_deg[NN];          // zero-init; k_scan re-zeroes after read
__device__ int   g_rowptr[NN];       // rebuilt every replay; consumed by fill
__device__ int   g_csrc[EE];
__device__ int   g_aggflag[128];     // lookback: agg+1 published, 0 = not ready

// ---------------- mma helpers -----------------------------------------------
__device__ __forceinline__ void ldsm4(uint32_t* d, const void* p) {
    uint32_t a = (uint32_t)__cvta_generic_to_shared(p);
    asm volatile("ldmatrix.sync.aligned.m8n8.x4.shared.b16 {%0,%1,%2,%3}, [%4];"
                 : "=r"(d[0]), "=r"(d[1]), "=r"(d[2]), "=r"(d[3]) : "r"(a));
}

__device__ __forceinline__ void mma_fp16(float* c, const uint32_t* a,
                                         uint32_t b0, uint32_t b1) {
    asm volatile(
        "mma.sync.aligned.m16n8k16.row.col.f32.f16.f16.f32 "
        "{%0,%1,%2,%3}, {%4,%5,%6,%7}, {%8,%9}, {%0,%1,%2,%3};"
        : "+f"(c[0]), "+f"(c[1]), "+f"(c[2]), "+f"(c[3])
        : "r"(a[0]), "r"(a[1]), "r"(a[2]), "r"(a[3]), "r"(b0), "r"(b1));
}

// ---------------- K1: FAT kernel -- fp16 GEMM  ||  degree count -------------
// Blocks [0, GEMM_BLKS): M=64 x N=128 GEMM; pair (2k, 2k+1) shares the A tile.
//   nblk=0 -> featsrc(fp16) + fused el/er;  nblk=1 -> skip (fp32).
//   W converted fp32->fp16 in-kernel (W_src/W_skip are L2-resident).
// Blocks [GEMM_BLKS, FAT_BLKS): count in-degrees + clear lookback flags.
__global__ void __launch_bounds__(256, 3) k_fat(
        const float* __restrict__ feat,
        const float* __restrict__ attn_l, const float* __restrict__ attn_r,
        const float* __restrict__ W_src, const float* __restrict__ b_src,
        const float* __restrict__ W_skip, const float* __restrict__ b_skip,
        const int* __restrict__ dst) {
    if (blockIdx.x >= GEMM_BLKS) {
        int b = blockIdx.x - GEMM_BLKS;
        if (b == 0 && threadIdx.x < 128) g_aggflag[threadIdx.x] = 0;
        int e = b * 256 + threadIdx.x;
        if (e < EE) atomicAdd(&g_deg[dst[e]], 1);
        return;
    }

    extern __shared__ __half smem[];
    __half* sA = smem;                      // 64 x PITCH
    __half* sB = sA + 64 * PITCH;           // 128 x PITCH
    __shared__ float sEl[4][64];
    __shared__ float sEr[4][64];

    const int t = threadIdx.x;
    const int nblk = blockIdx.x & 1;
    const int row0 = (blockIdx.x >> 1) * 64;
    const float* W = nblk ? W_skip : W_src;
    const float* bias = nblk ? b_skip : b_src;

    // ---- A tile (fp32 -> fp16): 64x128 = 2048 float4, 256 thr x 8 ----
#pragma unroll
    for (int i = 0; i < 8; i++) {
        int id = t + i * 256;             // 0..2047
        int r = id >> 5;                  // 0..63
        int q = (id & 31) << 2;           // 0..124
        float4 v = make_float4(0.f, 0.f, 0.f, 0.f);
        if (row0 + r < NN)
            v = *(const float4*)&feat[(size_t)(row0 + r) * 128 + q];
        __half2* p = (__half2*)&sA[r * PITCH + q];
        p[0] = __floats2half2_rn(v.x, v.y);
        p[1] = __floats2half2_rn(v.z, v.w);
    }
    // ---- B tile (fp32 W -> fp16): 128x128 = 4096 float4, 256 thr x 16 ------
#pragma unroll
    for (int i = 0; i < 16; i++) {
        int id = t + i * 256;             // 0..4095
        int r = id >> 5;                  // 0..127
        int q = (id & 31) << 2;
        float4 v = *(const float4*)&W[(size_t)r * 128 + q];
        __half2* p = (__half2*)&sB[r * PITCH + q];
        p[0] = __floats2half2_rn(v.x, v.y);
        p[1] = __floats2half2_rn(v.z, v.w);
    }
    __syncthreads();

    // ---- warp tiling: 8 warps in 2(M) x 4(N); each 32(M) x 32(N) ----
    const int wid = t >> 5, lane = t & 31;
    const int m0w = (wid >> 2) * 32;
    const int n0w = (wid & 3) * 32;

    float acc[2][4][4];
#pragma unroll
    for (int mt = 0; mt < 2; mt++)
#pragma unroll
        for (int nt = 0; nt < 4; nt++)
#pragma unroll
            for (int f = 0; f < 4; f++) acc[mt][nt][f] = 0.f;

#pragma unroll
    for (int kc = 0; kc < 8; kc++) {
        const int k0 = kc * 16;
        uint32_t a[2][4];
#pragma unroll
        for (int mt = 0; mt < 2; mt++) {
            int r = m0w + mt * 16 + (lane & 7) + ((lane >> 3) & 1) * 8;
            int c = k0 + (lane >> 4) * 8;
            ldsm4(a[mt], &sA[r * PITCH + c]);
        }
        uint32_t b[2][4];
#pragma unroll
        for (int np = 0; np < 2; np++) {
            int r = n0w + np * 16 + (lane & 7) + (lane >> 4) * 8;
            int c = k0 + ((lane >> 3) & 1) * 8;
            ldsm4(b[np], &sB[r * PITCH + c]);
        }
#pragma unroll
        for (int mt = 0; mt < 2; mt++)
#pragma unroll
            for (int nt = 0; nt < 4; nt++)
                mma_fp16(acc[mt][nt], a[mt],
                         b[nt >> 1][(nt & 1) * 2], b[nt >> 1][(nt & 1) * 2 + 1]);
    }

    // ---- epilogue: bias + store; fused el/er for nblk==0 --------------------
    const int g = lane >> 2, c2 = (lane & 3) * 2;
    const int head = wid & 3;      // this warp's 32 cols = one head
    float elp[2][2] = {{0.f, 0.f}, {0.f, 0.f}};
    float erp[2][2] = {{0.f, 0.f}, {0.f, 0.f}};
#pragma unroll
    for (int mt = 0; mt < 2; mt++) {
        int rbase = row0 + m0w + mt * 16 + g;
#pragma unroll
        for (int nt = 0; nt < 4; nt++) {
            int col = n0w + nt * 8 + c2;
            float b0 = bias[col];
            float b1 = bias[col + 1];
            float f0 = acc[mt][nt][0] + b0, f1 = acc[mt][nt][1] + b1;
            float f2 = acc[mt][nt][2] + b0, f3 = acc[mt][nt][3] + b1;
            if (nblk == 0) {
                if (rbase < NN)
                    *(__half2*)&g_fsh[(size_t)rbase * 128 + col] = __floats2half2_rn(f0, f1);
                if (rbase + 8 < NN)
                    *(__half2*)&g_fsh[(size_t)(rbase + 8) * 128 + col] = __floats2half2_rn(f2, f3);
                float al0 = attn_l[col], al1 = attn_l[col + 1];
                float ar0 = attn_r[col], ar1 = attn_r[col + 1];
                elp[mt][0] += f0 * al0 + f1 * al1;
                elp[mt][1] += f2 * al0 + f3 * al1;
                erp[mt][0] += f0 * ar0 + f1 * ar1;
                erp[mt][1] += f2 * ar0 + f3 * ar1;
            } else {
                if (rbase < NN)
                    *(float2*)&g_skip[(size_t)rbase * 128 + col] = make_float2(f0, f1);
                if (rbase + 8 < NN)
                    *(float2*)&g_skip[(size_t)(rbase + 8) * 128 + col] = make_float2(f2, f3);
            }
        }
    }
    if (nblk == 0) {
        // reduce across the lane quad (lanes sharing g)
#pragma unroll
        for (int mt = 0; mt < 2; mt++)
#pragma unroll
            for (int hf = 0; hf < 2; hf++) {
                elp[mt][hf] += __shfl_xor_sync(0xffffffffu, elp[mt][hf], 1);
                elp[mt][hf] += __shfl_xor_sync(0xffffffffu, elp[mt][hf], 2);
                erp[mt][hf] += __shfl_xor_sync(0xffffffffu, erp[mt][hf], 1);
                erp[mt][hf] += __shfl_xor_sync(0xffffffffu, erp[mt][hf], 2);
            }
        if ((lane & 3) == 0) {
#pragma unroll
            for (int mt = 0; mt < 2; mt++)
#pragma unroll
                for (int hf = 0; hf < 2; hf++) {
                    int lr = m0w + mt * 16 + g + hf * 8;   // 0..63
                    sEl[head][lr] = elp[mt][hf];
                    sEr[head][lr] = erp[mt][hf];
                }
        }
        __syncthreads();
        int lr = t >> 2, h = t & 3;   // 64 rows x 4 heads
        if (row0 + lr < NN) {
            g_el[(row0 + lr) * 4 + h] = sEl[h][lr];
            g_er[(row0 + lr) * 4 + h] = sEr[h][lr];
        }
    }
}

// ---------------- K2: single-launch decoupled-lookback scan ------------------
// 98 blocks x 1024. Each block: local scan of its g_deg chunk (re-zeroing it),
// publish aggregate (agg+1, release), sum all predecessor aggregates (acquire
// spin; all 98 blocks co-resident -> no deadlock), write exclusive rowptr.
__global__ void __launch_bounds__(1024) k_scan() {
    __shared__ int wsum[32];
    __shared__ int s_off;
    const int t = threadIdx.x;
    const int b = blockIdx.x;
    const int lane = t & 31, w = t >> 5;
    if (t == 0) s_off = 0;
    const int i = b * 1024 + t;
    int v = (i < NN) ? g_deg[i] : 0;
    if (i < NN) g_deg[i] = 0;             // reset for next replay
    int x = v;
#pragma unroll
    for (int off = 1; off < 32; off <<= 1) {
        int y = __shfl_up_sync(0xffffffffu, x, off);
        if (lane >= off) x += y;
    }
    if (lane == 31) wsum[w] = x;
    __syncthreads();
    if (w == 0) {
        int y = wsum[lane];
#pragma unroll
        for (int off = 1; off < 32; off <<= 1) {
            int z = __shfl_up_sync(0xffffffffu, y, off);
            if (lane >= off) y += z;
        }
        wsum[lane] = y;
    }
    __syncthreads();
    int incl = x + (w > 0 ? wsum[w - 1] : 0);     // block-inclusive prefix
    if (t == 1023) {                               // publish block aggregate
        int agg = incl + 1;
        asm volatile("st.global.release.gpu.b32 [%0], %1;"
                     :: "l"(&g_aggflag[b]), "r"(agg) : "memory");
    }
    if (t < b) {                                   // lookback (b <= 97 < 1024)
        int y;
        do {
            asm volatile("ld.global.acquire.gpu.b32 %0, [%1];"
                         : "=r"(y) : "l"(&g_aggflag[t]) : "memory");
        } while (y == 0);
        atomicAdd(&s_off, y - 1);
    }
    __syncthreads();
    if (i < NN) g_rowptr[i] = s_off + incl - v;   // global exclusive prefix
}

// ---------------- K3: fill CSR (atomics consume g_rowptr in place) ----------
__global__ void k_fill(const int* __restrict__ src, const int* __restrict__ dst) {
    int i = blockIdx.x * blockDim.x + threadIdx.x;
    if (i < EE) {
        int slot = atomicAdd(&g_rowptr[dst[i]], 1);
        g_csrc[slot] = src[i];
    }
}

// ---------------- K4: per-node softmax + aggregate + gate + LN + PReLU ------
// Shifted CSR: start = rowptr[n-1] (or 0), end = rowptr[n].
__global__ void k_node(const float* __restrict__ W_gate, const float* __restrict__ b_gate,
                       const float* __restrict__ ln_g, const float* __restrict__ ln_b,
                       const float* __restrict__ prelu_a, float* __restrict__ out) {
    int gid = blockIdx.x * blockDim.x + threadIdx.x;
    int n = gid >> 5;
    int lane = threadIdx.x & 31;
    if (n >= NN) return;
    const int h = lane >> 3;

    int start = (n == 0) ? 0 : g_rowptr[n - 1];
    int end = g_rowptr[n];
    int deg = end - start;
    float erh = g_er[n * 4 + h];

    float4 acc = make_float4(0.f, 0.f, 0.f, 0.f);
    float sumex = 0.f;
    int k = start;
    for (; k + 3 < end; k += 4) {
        int s0 = g_csrc[k], s1 = g_csrc[k + 1];
        int s2 = g_csrc[k + 2], s3 = g_csrc[k + 3];
        float e0 = g_el[s0 * 4 + h] + erh;
        float e1 = g_el[s1 * 4 + h] + erh;
        float e2 = g_el[s2 * 4 + h] + erh;
        float e3 = g_el[s3 * 4 + h] + erh;
        uint2 u0 = *(const uint2*)&g_fsh[(size_t)s0 * 128 + 4 * lane];
        uint2 u1 = *(const uint2*)&g_fsh[(size_t)s1 * 128 + 4 * lane];
        uint2 u2 = *(const uint2*)&g_fsh[(size_t)s2 * 128 + 4 * lane];
        uint2 u3 = *(const uint2*)&g_fsh[(size_t)s3 * 128 + 4 * lane];
        e0 = (e0 >= 0.f) ? e0 : 0.2f * e0;
        e1 = (e1 >= 0.f) ? e1 : 0.2f * e1;
        e2 = (e2 >= 0.f) ? e2 : 0.2f * e2;
        e3 = (e3 >= 0.f) ? e3 : 0.2f * e3;
        float x0 = __expf(e0), x1 = __expf(e1), x2 = __expf(e2), x3 = __expf(e3);
        sumex += x0 + x1 + x2 + x3;
        float2 a0 = __half22float2(*(__half2*)&u0.x), b0 = __half22float2(*(__half2*)&u0.y);
        float2 a1 = __half22float2(*(__half2*)&u1.x), b1 = __half22float2(*(__half2*)&u1.y);
        float2 a2 = __half22float2(*(__half2*)&u2.x), b2 = __half22float2(*(__half2*)&u2.y);
        float2 a3 = __half22float2(*(__half2*)&u3.x), b3 = __half22float2(*(__half2*)&u3.y);
        acc.x += x0 * a0.x + x1 * a1.x + x2 * a2.x + x3 * a3.x;
        acc.y += x0 * a0.y + x1 * a1.y + x2 * a2.y + x3 * a3.y;
        acc.z += x0 * b0.x + x1 * b1.x + x2 * b2.x + x3 * b3.x;
        acc.w += x0 * b0.y + x1 * b1.y + x2 * b2.y + x3 * b3.y;
    }
    for (; k < end; k++) {
        int s = g_csrc[k];
        float e = g_el[s * 4 + h] + erh;
        e = (e >= 0.f) ? e : 0.2f * e;
        float ex = __expf(e);
        sumex += ex;
        uint2 u = *(const uint2*)&g_fsh[(size_t)s * 128 + 4 * lane];
        float2 a = __half22float2(*(__half2*)&u.x), b = __half22float2(*(__half2*)&u.y);
        acc.x += ex * a.x; acc.y += ex * a.y;
        acc.z += ex * b.x; acc.w += ex * b.y;
    }
    float4 rst;
    if (deg > 0) {
        float inv = 1.0f / sumex;
        rst = make_float4(acc.x * inv, acc.y * inv, acc.z * inv, acc.w * inv);
    } else {
        rst = make_float4(0.f, 0.f, 0.f, 0.f);
    }

    float4 sk = *(const float4*)&g_skip[(size_t)n * 128 + 4 * lane];
    float4 w1 = *(const float4*)&W_gate[4 * lane];
    float4 w2 = *(const float4*)&W_gate[128 + 4 * lane];
    float4 w3 = *(const float4*)&W_gate[256 + 4 * lane];
    float gacc = rst.x * w1.x + rst.y * w1.y + rst.z * w1.z + rst.w * w1.w
               + sk.x * w2.x + sk.y * w2.y + sk.z * w2.z + sk.w * w2.w
               + (rst.x - sk.x) * w3.x + (rst.y - sk.y) * w3.y
               + (rst.z - sk.z) * w3.z + (rst.w - sk.w) * w3.w;
#pragma unroll
    for (int off = 16; off >= 1; off >>= 1)
        gacc += __shfl_xor_sync(0xffffffffu, gacc, off);
    float gate = 1.0f / (1.0f + __expf(-(gacc + b_gate[0])));
    float4 x = make_float4(gate * rst.x + (1.f - gate) * sk.x,
                           gate * rst.y + (1.f - gate) * sk.y,
                           gate * rst.z + (1.f - gate) * sk.z,
                           gate * rst.w + (1.f - gate) * sk.w);

    float s1 = x.x + x.y + x.z + x.w;
    float s2 = x.x * x.x + x.y * x.y + x.z * x.z + x.w * x.w;
#pragma unroll
    for (int off = 16; off >= 1; off >>= 1) {
        s1 += __shfl_xor_sync(0xffffffffu, s1, off);
        s2 += __shfl_xor_sync(0xffffffffu, s2, off);
    }
    float mean = s1 * (1.0f / 128.0f);
    float var = s2 * (1.0f / 128.0f) - mean * mean;
    float inv = rsqrtf(var + 1e-5f);
    float4 g4 = *(const float4*)&ln_g[4 * lane];
    float4 b4 = *(const float4*)&ln_b[4 * lane];
    float alpha = prelu_a[0];
    float y0 = (x.x - mean) * inv * g4.x + b4.x;
    float y1 = (x.y - mean) * inv * g4.y + b4.y;
    float y2 = (x.z - mean) * inv * g4.z + b4.z;
    float y3 = (x.w - mean) * inv * g4.w + b4.w;
    y0 = (y0 >= 0.f) ? y0 : alpha * y0;
    y1 = (y1 >= 0.f) ? y1 : alpha * y1;
    y2 = (y2 >= 0.f) ? y2 : alpha * y2;
    y3 = (y3 >= 0.f) ? y3 : alpha * y3;
    *(float4*)&out[(size_t)n * 128 + 4 * lane] = make_float4(y0, y1, y2, y3);
}

// ---------------- launcher ---------------------------------------------------
extern "C" void kernel_launch(void* const* d_in, const int* in_sizes, int n_in,
                              void* d_out, int out_size) {
    const float* feat    = (const float*)d_in[0];
    const int*   src     = (const int*)d_in[1];
    const int*   dst     = (const int*)d_in[2];
    const float* W_src   = (const float*)d_in[3];
    const float* b_src   = (const float*)d_in[4];
    const float* attn_l  = (const float*)d_in[5];
    const float* attn_r  = (const float*)d_in[6];
    const float* W_skip  = (const float*)d_in[7];
    const float* b_skip  = (const float*)d_in[8];
    const float* W_gate  = (const float*)d_in[9];
    const float* b_gate  = (const float*)d_in[10];
    const float* ln_g    = (const float*)d_in[11];
    const float* ln_b    = (const float*)d_in[12];
    const float* prelu_a = (const float*)d_in[13];
    float* out = (float*)d_out;

    // smem: (64 + 128) * PITCH * 2B = 52224
    const int FAT_SMEM = (64 + 128) * PITCH * (int)sizeof(__half);
    static int smem_set = 0;
    if (!smem_set) {
        cudaFuncSetAttribute(k_fat, cudaFuncAttributeMaxDynamicSharedMemorySize, FAT_SMEM);
        smem_set = 1;
    }

    k_fat<<<FAT_BLKS, 256, FAT_SMEM>>>(feat, attn_l, attn_r,
                                       W_src, b_src, W_skip, b_skip, dst);
    k_scan<<<98, 1024>>>();
    k_fill<<<(EE + 255) / 256, 256>>>(src, dst);
    k_node<<<(NN * 32 + 255) / 256, 256>>>(W_gate, b_gate, ln_g, ln_b, prelu_a, out);
}